// round 16
// baseline (speedup 1.0000x reference)
#include <cuda_runtime.h>
#include <cstdint>

#define BB 1024
#define TT 4096
#define SS 8
#define EE 8
#define PHS 64              // scan steps per cp.async phase
#define NPH (TT / PHS)
#define CPB 8               // chains per block (4 warps x 2 chains SIMT)
#define THREADS 128

#define FIXSCALE 1048576.0f         // 2^20 folded into Wr2
#define FIXINV   (1.0f / 1048576.0f)

// Scratch (no cudaMalloc allowed)
__device__ float g_preds[(size_t)BB * TT * SS];   // 134 MB trajectory
__device__ float g_dt[TT];

using ull = unsigned long long;

// ---------------- f32x2 packed helpers ----------------
__device__ __forceinline__ ull pk2(float lo, float hi) {
    ull r; asm("mov.b64 %0, {%1, %2};" : "=l"(r) : "f"(lo), "f"(hi)); return r;
}
__device__ __forceinline__ void up2(ull a, float& lo, float& hi) {
    asm("mov.b64 {%0, %1}, %2;" : "=f"(lo), "=f"(hi) : "l"(a));
}
__device__ __forceinline__ ull fma2(ull a, ull b, ull c) {
    ull r; asm("fma.rn.f32x2 %0, %1, %2, %3;" : "=l"(r) : "l"(a), "l"(b), "l"(c)); return r;
}
__device__ __forceinline__ ull mul2(ull a, ull b) {
    ull r; asm("mul.rn.f32x2 %0, %1, %2;" : "=l"(r) : "l"(a), "l"(b)); return r;
}
__device__ __forceinline__ ull add2(ull a, ull b) {
    ull r; asm("add.rn.f32x2 %0, %1, %2;" : "=l"(r) : "l"(a), "l"(b)); return r;
}

// hardware tanh (MUFU.TANH): ~5e-4 max abs err, 1 instr
__device__ __forceinline__ float hw_tanh(float z) {
    float r; asm("tanh.approx.f32 %0, %1;" : "=f"(r) : "f"(z));
    return r;
}

__device__ __forceinline__ void cpa16(void* dst, const void* src) {
    unsigned s = (unsigned)__cvta_generic_to_shared(dst);
    asm volatile("cp.async.cg.shared.global [%0], [%1], 16;" :: "r"(s), "l"(src));
}

// ---------------------------------------------------------------------------
__global__ void dt_kernel(const float* __restrict__ t) {
    int i = blockIdx.x * blockDim.x + threadIdx.x;
    if (i < TT) g_dt[i] = (i < TT - 1) ? (t[i + 1] - t[i]) : 0.0f;
}

// ---------------------------------------------------------------------------
// Sequential Euler scan: 16 lanes per chain, 2 chains per warp (SIMT),
// 4 warps/block, 512 warps. Lane u (=lane&15) owns hidden units j = u, u+16.
//
// Reduction: single-stage hardware REDUX. rhs partials are computed pre-scaled
// by 2^20 (folded into Wr2 at load), rounded to s32 (cvt.rni), summed over the
// 16-lane group with __reduce_add_sync (REDUX.SUM -> result in all lanes),
// converted back, and the 2^-20 is folded into dt for the Euler update.
// Replaces the 5-stage / 20-SHFL32 shuffle tree (~150 cy) with ~75 cy.
__global__ __launch_bounds__(THREADS, 1)
void scan_kernel(const float* __restrict__ x,    // [B,T,E]
                 const float* __restrict__ y0,   // [B,S]
                 const float* __restrict__ Wr1,  // [S+E, 32]
                 const float* __restrict__ br1,  // [32]
                 const float* __restrict__ Wr2,  // [32, S]
                 const float* __restrict__ br2)  // [S]
{
    __shared__ __align__(16) float sx[2][CPB][PHS * EE];  // 32 KB x-staging
    __shared__ __align__(16) float sdt[2][PHS];           // dt staging

    const int tid  = threadIdx.x;
    const int lane = tid & 31;
    const int wid  = tid >> 5;
    const int u    = lane & 15;                 // lane within 16-group
    const int grp  = lane >> 4;                 // chain within warp
    const int cloc = wid * 2 + grp;             // chain slot in block
    const int chain = blockIdx.x * CPB + cloc;
    const unsigned gmask = grp ? 0xFFFF0000u : 0x0000FFFFu;  // REDUX group

    // ---- register-resident weights (packed pairs), units j = u + 16m ----
    // w2p pre-scaled by 2^20 so the s32 fixed-point reduction needs no extra mul.
    ull wy[2][4], we[2][4], w2p[2][4], b1p[2];
#pragma unroll
    for (int m = 0; m < 2; ++m) {
        const int j = u + 16 * m;
#pragma unroll
        for (int k = 0; k < 4; ++k) {
            wy[m][k]  = pk2(Wr1[(2 * k) * 32 + j],     Wr1[(2 * k + 1) * 32 + j]);
            we[m][k]  = pk2(Wr1[(8 + 2 * k) * 32 + j], Wr1[(9 + 2 * k) * 32 + j]);
            w2p[m][k] = pk2(Wr2[j * 8 + 2 * k] * FIXSCALE,
                            Wr2[j * 8 + 2 * k + 1] * FIXSCALE);
        }
        b1p[m] = pk2(br1[j], 0.0f);   // bias in lo slot; hi stays 0 through chain
    }
    ull b2p[4];
#pragma unroll
    for (int k = 0; k < 4; ++k) b2p[k] = pk2(br2[2 * k], br2[2 * k + 1]);

    // ---- initial state (replicated per lane, natural order) ----
    ull yp[4];
    {
        const float4* q = (const float4*)(y0 + (size_t)chain * SS);
        float4 A = q[0], B = q[1];
        yp[0] = pk2(A.x, A.y); yp[1] = pk2(A.z, A.w);
        yp[2] = pk2(B.x, B.y); yp[3] = pk2(B.z, B.w);
    }

    // ---- phase staging: 8 chains x 512 floats = 1024 x 16B; 8 per thread ----
    auto issue = [&](int ph, int buf) {
#pragma unroll
        for (int q = 0; q < 8; ++q) {
            const int idx = tid + q * THREADS;    // 0..1023
            const int c   = idx >> 7;             // chain
            const int off = idx & 127;            // 16B chunk within chain
            cpa16(&sx[buf][c][off * 4],
                  x + ((size_t)(blockIdx.x * CPB + c) * TT + (size_t)ph * PHS) * EE + off * 4);
        }
        if (tid < 16) cpa16(&sdt[buf][tid * 4], g_dt + ph * PHS + tid * 4);
        asm volatile("cp.async.commit_group;");
    };

    issue(0, 0);
    asm volatile("cp.async.wait_group 0;");
    __syncthreads();

    float* pp = g_preds + (size_t)chain * TT * SS;
    int buf = 0;

    for (int ph = 0; ph < NPH; ++ph) {
        if (ph + 1 < NPH) {
            issue(ph + 1, buf ^ 1);
            asm volatile("cp.async.wait_group 1;");
        }
        __syncthreads();
        const float* eb  = sx[buf][cloc];
        const float* dtb = sdt[buf];

#pragma unroll 8
        for (int i = 0; i < PHS; ++i) {
            const float dt = dtb[i];
            const ull dt2  = pk2(dt, dt);
            const float dts = dt * FIXINV;        // un-scale folded into dt
            const ull dt2s = pk2(dts, dts);
            // prefold y + dt*br2 (all 4 pairs) — parallel with z-dot
            ull ybo[4];
#pragma unroll
            for (int k = 0; k < 4; ++k) ybo[k] = fma2(dt2, b2p[k], yp[k]);

            // e as 2 x LDS.128 (4 packed pairs, natural order)
            const ulonglong2* ev = (const ulonglong2*)(eb + i * 8);
            const ulonglong2 eA = ev[0], eB = ev[1];

            // z_j = br1 + e.We + y.Wy — two parallel 4-deep chains + merge
            float h[2];
#pragma unroll
            for (int m = 0; m < 2; ++m) {
                ull c = fma2(eA.x, we[m][0], b1p[m]);
                ull a = mul2(yp[0], wy[m][0]);
                c = fma2(eA.y, we[m][1], c);
                a = fma2(yp[1], wy[m][1], a);
                c = fma2(eB.x, we[m][2], c);
                a = fma2(yp[2], wy[m][2], a);
                c = fma2(eB.y, we[m][3], c);
                a = fma2(yp[3], wy[m][3], a);
                const ull s = add2(a, c);
                float lo, hi; up2(s, lo, hi);
                h[m] = hw_tanh(lo + hi);
            }

            // partial rhs pairs, pre-scaled by 2^20 (in w2p)
            const ull h0d = pk2(h[0], h[0]);
            const ull h1d = pk2(h[1], h[1]);
            ull p0 = fma2(h1d, w2p[1][0], mul2(h0d, w2p[0][0]));
            ull p1 = fma2(h1d, w2p[1][1], mul2(h0d, w2p[0][1]));
            ull p2 = fma2(h1d, w2p[1][2], mul2(h0d, w2p[0][2]));
            ull p3 = fma2(h1d, w2p[1][3], mul2(h0d, w2p[0][3]));

            // --- preds store inside the reduction window (pre-update y) ---
            if (u == 0) {
                float f0, f1, f2, f3, f4, f5, f6, f7;
                up2(yp[0], f0, f1); up2(yp[1], f2, f3);
                up2(yp[2], f4, f5); up2(yp[3], f6, f7);
                float4* oo = (float4*)pp;
                oo[0] = make_float4(f0, f1, f2, f3);
                oo[1] = make_float4(f4, f5, f6, f7);
            }
            pp += SS;

            // unpack -> round to s32 -> one-stage REDUX over the 16-lane group
            float pf[8];
            up2(p0, pf[0], pf[1]); up2(p1, pf[2], pf[3]);
            up2(p2, pf[4], pf[5]); up2(p3, pf[6], pf[7]);
            int qi[8];
#pragma unroll
            for (int s = 0; s < 8; ++s) qi[s] = __float2int_rn(pf[s]);
#pragma unroll
            for (int s = 0; s < 8; ++s) qi[s] = __reduce_add_sync(gmask, qi[s]);
            float qf[8];
#pragma unroll
            for (int s = 0; s < 8; ++s) qf[s] = __int2float_rn(qi[s]);

            // Euler update (dt[T-1]=0 makes the final update a no-op)
            yp[0] = fma2(dt2s, pk2(qf[0], qf[1]), ybo[0]);
            yp[1] = fma2(dt2s, pk2(qf[2], qf[3]), ybo[1]);
            yp[2] = fma2(dt2s, pk2(qf[4], qf[5]), ybo[2]);
            yp[3] = fma2(dt2s, pk2(qf[6], qf[7]), ybo[3]);
        }
        __syncthreads();     // all reads of sx[buf] done before next issue overwrites it
        buf ^= 1;
    }
}

// ---------------------------------------------------------------------------
// Head: out = relu(preds @ W1 + b1) @ W2 + b2 — fully register-resident weights
__global__ __launch_bounds__(256)
void head_kernel(const float* __restrict__ W1, const float* __restrict__ b1,
                 const float* __restrict__ W2, const float* __restrict__ b2,
                 float* __restrict__ out)
{
    float w1[8][10], bb1[10], w2[10][2];
#pragma unroll
    for (int s = 0; s < 8; ++s)
#pragma unroll
        for (int i = 0; i < 10; ++i) w1[s][i] = __ldg(&W1[s * 10 + i]);
#pragma unroll
    for (int i = 0; i < 10; ++i) {
        bb1[i]   = __ldg(&b1[i]);
        w2[i][0] = __ldg(&W2[i * 2 + 0]);
        w2[i][1] = __ldg(&W2[i * 2 + 1]);
    }
    const float c0 = __ldg(&b2[0]), c1 = __ldg(&b2[1]);

    const int nt  = gridDim.x * blockDim.x;
    const int tid = blockIdx.x * blockDim.x + threadIdx.x;
    const int NPOS = BB * TT;

    for (int pos = tid; pos < NPOS; pos += nt) {
        const float4* ypt = (const float4*)(g_preds + (size_t)pos * SS);
        const float4 A = ypt[0], B = ypt[1];
        const float yv[8] = {A.x, A.y, A.z, A.w, B.x, B.y, B.z, B.w};
        float o0 = c0, o1 = c1;
#pragma unroll
        for (int i = 0; i < 10; ++i) {
            float hz = bb1[i];
#pragma unroll
            for (int s = 0; s < 8; ++s) hz = fmaf(yv[s], w1[s][i], hz);
            hz = fmaxf(hz, 0.0f);
            o0 = fmaf(hz, w2[i][0], o0);
            o1 = fmaf(hz, w2[i][1], o1);
        }
        *(float2*)(out + (size_t)pos * 2) = make_float2(o0, o1);
    }
}

// ---------------------------------------------------------------------------
extern "C" void kernel_launch(void* const* d_in, const int* in_sizes, int n_in,
                              void* d_out, int out_size) {
    const float* x   = (const float*)d_in[0];
    const float* t   = (const float*)d_in[1];
    const float* y0  = (const float*)d_in[2];
    const float* Wr1 = (const float*)d_in[3];
    const float* br1 = (const float*)d_in[4];
    const float* Wr2 = (const float*)d_in[5];
    const float* br2 = (const float*)d_in[6];
    const float* W1  = (const float*)d_in[7];
    const float* b1  = (const float*)d_in[8];
    const float* W2  = (const float*)d_in[9];
    const float* b2  = (const float*)d_in[10];
    float* out = (float*)d_out;

    dt_kernel<<<16, 256>>>(t);
    scan_kernel<<<BB / CPB, THREADS>>>(x, y0, Wr1, br1, Wr2, br2);
    head_kernel<<<2048, 256>>>(W1, b1, W2, b2, out);
}

// round 17
// speedup vs baseline: 6.4638x; 6.4638x over previous
#include <cuda_runtime.h>
#include <cstdint>

#define BB 1024
#define TT 4096
#define SS 8
#define EE 8
#define PHS 64              // scan steps per cp.async phase
#define NPH (TT / PHS)
#define CPB 8               // chains per block (4 warps x 2 chains SIMT)
#define THREADS 128

// Scratch (no cudaMalloc allowed)
__device__ float g_dt[TT];

using ull = unsigned long long;

// ---------------- f32x2 packed helpers ----------------
__device__ __forceinline__ ull pk2(float lo, float hi) {
    ull r; asm("mov.b64 %0, {%1, %2};" : "=l"(r) : "f"(lo), "f"(hi)); return r;
}
__device__ __forceinline__ void up2(ull a, float& lo, float& hi) {
    asm("mov.b64 {%0, %1}, %2;" : "=f"(lo), "=f"(hi) : "l"(a));
}
__device__ __forceinline__ ull fma2(ull a, ull b, ull c) {
    ull r; asm("fma.rn.f32x2 %0, %1, %2, %3;" : "=l"(r) : "l"(a), "l"(b), "l"(c)); return r;
}
__device__ __forceinline__ ull mul2(ull a, ull b) {
    ull r; asm("mul.rn.f32x2 %0, %1, %2;" : "=l"(r) : "l"(a), "l"(b)); return r;
}
__device__ __forceinline__ ull add2(ull a, ull b) {
    ull r; asm("add.rn.f32x2 %0, %1, %2;" : "=l"(r) : "l"(a), "l"(b)); return r;
}

// hardware tanh (MUFU.TANH): ~5e-4 max abs err, 1 instr
__device__ __forceinline__ float hw_tanh(float z) {
    float r; asm("tanh.approx.f32 %0, %1;" : "=f"(r) : "f"(z));
    return r;
}

__device__ __forceinline__ void cpa16(void* dst, const void* src) {
    unsigned s = (unsigned)__cvta_generic_to_shared(dst);
    asm volatile("cp.async.cg.shared.global [%0], [%1], 16;" :: "r"(s), "l"(src));
}

// ---------------------------------------------------------------------------
__global__ void dt_kernel(const float* __restrict__ t) {
    int i = blockIdx.x * blockDim.x + threadIdx.x;
    if (i < TT) g_dt[i] = (i < TT - 1) ? (t[i + 1] - t[i]) : 0.0f;
}

// ---------------------------------------------------------------------------
// Sequential Euler scan WITH FUSED HEAD: 16 lanes per chain, 2 chains per
// warp (SIMT), 4 warps/block, 512 warps. Lane u (=lane&15) owns hidden units
// j = u, u+16 of the recurrent MLP, and (for u<10) head hidden unit u.
//
// rhs reduction (permuted slots, 20 SHFL32/step):
//   reduce-scatter (mask 8) -> 3-round butterfly (1,2,4) -> own-half update
//   -> all-gather (mask 8)
// The head partial o = relu(b1+y.W1[:,u])*(W2[u,0],W2[u,1]) rides the same
// four masks {8,1,2,4} as a full 16-lane all-reduce — no extra stages.
// out[b][t][:] is stored directly (STG.64, lane 0); no preds buffer at all.
__global__ __launch_bounds__(THREADS, 1)
void scan_kernel(const float* __restrict__ x,    // [B,T,E]
                 const float* __restrict__ y0,   // [B,S]
                 const float* __restrict__ Wr1,  // [S+E, 32]
                 const float* __restrict__ br1,  // [32]
                 const float* __restrict__ Wr2,  // [32, S]
                 const float* __restrict__ br2,  // [S]
                 const float* __restrict__ W1,   // [S, 10]  head
                 const float* __restrict__ b1,   // [10]
                 const float* __restrict__ W2,   // [10, 2]
                 const float* __restrict__ b2,   // [2]
                 float* __restrict__ out)        // [B, T, 2]
{
    __shared__ __align__(16) float sx[2][CPB][PHS * EE];  // 32 KB x-staging
    __shared__ __align__(16) float sdt[2][PHS];           // dt staging

    const int tid  = threadIdx.x;
    const int lane = tid & 31;
    const int wid  = tid >> 5;
    const int u    = lane & 15;                 // lane within 16-group
    const int grp  = lane >> 4;                 // chain within warp
    const int cloc = wid * 2 + grp;             // chain slot in block
    const int chain = blockIdx.x * CPB + cloc;

    const int o = (u >> 3) & 1;                 // own-half selector
    int cpm[4];                                 // slot k -> component pair
    cpm[0] = 2 * o;       cpm[1] = 2 * o + 1;
    cpm[2] = 2 * (1 - o); cpm[3] = 2 * (1 - o) + 1;

    // ---- register-resident recurrent weights (packed pairs), j = u + 16m ----
    ull wy[2][4], we[2][4], w2p[2][4], b1p[2];
#pragma unroll
    for (int m = 0; m < 2; ++m) {
        const int j = u + 16 * m;
#pragma unroll
        for (int k = 0; k < 4; ++k) {
            const int cp = cpm[k];
            wy[m][k]  = pk2(Wr1[(2 * cp) * 32 + j],    Wr1[(2 * cp + 1) * 32 + j]);
            we[m][k]  = pk2(Wr1[(8 + 2 * k) * 32 + j], Wr1[(9 + 2 * k) * 32 + j]);
            w2p[m][k] = pk2(Wr2[j * 8 + 2 * cp],       Wr2[j * 8 + 2 * cp + 1]);
        }
        b1p[m] = pk2(br1[j], 0.0f);   // bias in lo slot; hi stays 0 through chain
    }
    ull b2o[2];                        // own-half br2 pairs (slots 0,1)
    b2o[0] = pk2(br2[2 * cpm[0]], br2[2 * cpm[0] + 1]);
    b2o[1] = pk2(br2[2 * cpm[1]], br2[2 * cpm[1] + 1]);

    // ---- head weights: lane u handles head hidden unit u (u < 10) ----
    ull w1c[4], w2h;                   // W1 column u in cpm slot order; W2 row u
    float b1h;
    if (u < 10) {
#pragma unroll
        for (int k = 0; k < 4; ++k) {
            const int cp = cpm[k];
            w1c[k] = pk2(W1[(2 * cp) * 10 + u], W1[(2 * cp + 1) * 10 + u]);
        }
        b1h = b1[u];
        w2h = pk2(W2[u * 2 + 0], W2[u * 2 + 1]);
    } else {
#pragma unroll
        for (int k = 0; k < 4; ++k) w1c[k] = 0;
        b1h = 0.0f;
        w2h = 0;
    }
    const ull hb2 = pk2(b2[0], b2[1]); // head output bias

    // ---- initial state into permuted slots ----
    ull yp[4];
    {
        const float4* q = (const float4*)(y0 + (size_t)chain * SS);
        float4 A = q[0], B = q[1];
        ull nat[4];
        nat[0] = pk2(A.x, A.y); nat[1] = pk2(A.z, A.w);
        nat[2] = pk2(B.x, B.y); nat[3] = pk2(B.z, B.w);
#pragma unroll
        for (int k = 0; k < 4; ++k) yp[k] = nat[cpm[k]];
    }

    // ---- phase staging: 8 chains x 512 floats = 1024 x 16B; 8 per thread ----
    auto issue = [&](int ph, int buf) {
#pragma unroll
        for (int q = 0; q < 8; ++q) {
            const int idx = tid + q * THREADS;    // 0..1023
            const int c   = idx >> 7;             // chain
            const int off = idx & 127;            // 16B chunk within chain
            cpa16(&sx[buf][c][off * 4],
                  x + ((size_t)(blockIdx.x * CPB + c) * TT + (size_t)ph * PHS) * EE + off * 4);
        }
        if (tid < 16) cpa16(&sdt[buf][tid * 4], g_dt + ph * PHS + tid * 4);
        asm volatile("cp.async.commit_group;");
    };

    issue(0, 0);
    asm volatile("cp.async.wait_group 0;");
    __syncthreads();

    float* po = out + (size_t)chain * TT * 2;
    int buf = 0;

    for (int ph = 0; ph < NPH; ++ph) {
        if (ph + 1 < NPH) {
            issue(ph + 1, buf ^ 1);
            asm volatile("cp.async.wait_group 1;");
        }
        __syncthreads();
        const float* eb  = sx[buf][cloc];
        const float* dtb = sdt[buf];

#pragma unroll 8
        for (int i = 0; i < PHS; ++i) {
            const float dt = dtb[i];
            const ull dt2 = pk2(dt, dt);
            // prefold y + dt*br2 on own half — parallel with z-dot
            const ull ybo0 = fma2(dt2, b2o[0], yp[0]);
            const ull ybo1 = fma2(dt2, b2o[1], yp[1]);

            // ---- fused head partial on PRE-update y (independent of rhs path)
            ull hacc = fma2(yp[1], w1c[1], mul2(yp[0], w1c[0]));
            ull hac2 = fma2(yp[3], w1c[3], mul2(yp[2], w1c[2]));
            hacc = add2(hacc, hac2);
            float hl, hh; up2(hacc, hl, hh);
            const float hz = fmaxf(hl + hh + b1h, 0.0f);
            ull ov = mul2(pk2(hz, hz), w2h);     // (hz*W2[u,0], hz*W2[u,1])

            // e as 2 x LDS.128 (4 packed pairs, natural order)
            const ulonglong2* ev = (const ulonglong2*)(eb + i * 8);
            const ulonglong2 eA = ev[0], eB = ev[1];

            // z_j = br1 + e.We + y.Wy — two parallel 4-deep chains + merge
            float h[2];
#pragma unroll
            for (int m = 0; m < 2; ++m) {
                ull c = fma2(eA.x, we[m][0], b1p[m]);
                ull a = mul2(yp[0], wy[m][0]);
                c = fma2(eA.y, we[m][1], c);
                a = fma2(yp[1], wy[m][1], a);
                c = fma2(eB.x, we[m][2], c);
                a = fma2(yp[2], wy[m][2], a);
                c = fma2(eB.y, we[m][3], c);
                a = fma2(yp[3], wy[m][3], a);
                const ull s = add2(a, c);
                float lo, hi; up2(s, lo, hi);
                h[m] = hw_tanh(lo + hi);
            }

            // partial rhs pairs (permuted slot order)
            const ull h0d = pk2(h[0], h[0]);
            const ull h1d = pk2(h[1], h[1]);
            ull p2 = fma2(h1d, w2p[1][2], mul2(h0d, w2p[0][2]));
            ull p3 = fma2(h1d, w2p[1][3], mul2(h0d, w2p[0][3]));

            // reduce-scatter (mask 8) + head all-reduce stage (mask 8)
            const ull t2 = __shfl_xor_sync(0xffffffffu, p2, 8);
            const ull t3 = __shfl_xor_sync(0xffffffffu, p3, 8);
            ov = add2(ov, __shfl_xor_sync(0xffffffffu, ov, 8));

            ull p0 = fma2(h1d, w2p[1][0], mul2(h0d, w2p[0][0]));
            ull p1 = fma2(h1d, w2p[1][1], mul2(h0d, w2p[0][1]));

            ull q0 = add2(p0, t2);
            ull q1 = add2(p1, t3);

            // 3-round butterfly (masks 1,2,4); head value rides the same rounds
#pragma unroll
            for (int mask = 1; mask < 8; mask <<= 1) {
                q0 = add2(q0, __shfl_xor_sync(0xffffffffu, q0, mask));
                q1 = add2(q1, __shfl_xor_sync(0xffffffffu, q1, mask));
                ov = add2(ov, __shfl_xor_sync(0xffffffffu, ov, mask));
            }

            // out[b][t][:] = head(pre-update y) — full sum present in all lanes
            if (u == 0) {
                const ull of = add2(ov, hb2);
                float o0, o1; up2(of, o0, o1);
                *(float2*)po = make_float2(o0, o1);
            }
            po += 2;

            // Euler update, own half only (dt[T-1]=0 -> final step no-op)
            yp[0] = fma2(dt2, q0, ybo0);
            yp[1] = fma2(dt2, q1, ybo1);

            // all-gather (mask 8): partner's updated own half = my other half
            yp[2] = __shfl_xor_sync(0xffffffffu, yp[0], 8);
            yp[3] = __shfl_xor_sync(0xffffffffu, yp[1], 8);
        }
        __syncthreads();     // all reads of sx[buf] done before next issue overwrites it
        buf ^= 1;
    }
}

// ---------------------------------------------------------------------------
extern "C" void kernel_launch(void* const* d_in, const int* in_sizes, int n_in,
                              void* d_out, int out_size) {
    const float* x   = (const float*)d_in[0];
    const float* t   = (const float*)d_in[1];
    const float* y0  = (const float*)d_in[2];
    const float* Wr1 = (const float*)d_in[3];
    const float* br1 = (const float*)d_in[4];
    const float* Wr2 = (const float*)d_in[5];
    const float* br2 = (const float*)d_in[6];
    const float* W1  = (const float*)d_in[7];
    const float* b1  = (const float*)d_in[8];
    const float* W2  = (const float*)d_in[9];
    const float* b2  = (const float*)d_in[10];
    float* out = (float*)d_out;

    dt_kernel<<<16, 256>>>(t);
    scan_kernel<<<BB / CPB, THREADS>>>(x, y0, Wr1, br1, Wr2, br2,
                                       W1, b1, W2, b2, out);
}